// round 2
// baseline (speedup 1.0000x reference)
#include <cuda_runtime.h>
#include <math.h>

#define Bb 2
#define Tt 2048
#define Ee 1024
#define Hh 16
#define Dd 64
#define Nn (Bb*Tt)      /* 4096 rows */
#define FF 4096
#define LN_EPS 1e-5f

// ---------------- scratch (allocation-free rule: __device__ globals) --------
__device__ float g_xn[Nn*Ee];
__device__ float g_q [Nn*Ee];
__device__ float g_k [Nn*Ee];
__device__ float g_v [Nn*Ee];
__device__ float g_att[Nn*Ee];
__device__ float g_x1[Nn*Ee];
__device__ float g_h [Nn*Ee];
__device__ float g_ff[(size_t)Nn*FF];

// ---------------- LayerNorm: one block (256 thr) per row of 1024 ------------
__global__ __launch_bounds__(256) void ln_kernel(
    const float* __restrict__ x, const float* __restrict__ gamma,
    const float* __restrict__ beta, float* __restrict__ y)
{
    int row = blockIdx.x;
    int tid = threadIdx.x;
    const float4* xp = (const float4*)(x + (size_t)row * Ee);
    float4 v = xp[tid];
    float s  = v.x + v.y + v.z + v.w;
    float sq = v.x*v.x + v.y*v.y + v.z*v.z + v.w*v.w;
    #pragma unroll
    for (int m = 16; m >= 1; m >>= 1) {
        s  += __shfl_xor_sync(0xffffffffu, s,  m);
        sq += __shfl_xor_sync(0xffffffffu, sq, m);
    }
    __shared__ float sh[16];
    int w = tid >> 5, l = tid & 31;
    if (l == 0) { sh[w] = s; sh[8 + w] = sq; }
    __syncthreads();
    if (tid < 32) {
        s  = (l < 8) ? sh[l]     : 0.f;
        sq = (l < 8) ? sh[8 + l] : 0.f;
        #pragma unroll
        for (int m = 4; m >= 1; m >>= 1) {
            s  += __shfl_xor_sync(0xffffffffu, s,  m);
            sq += __shfl_xor_sync(0xffffffffu, sq, m);
        }
        if (l == 0) { sh[0] = s; sh[8] = sq; }
    }
    __syncthreads();
    float mu  = sh[0] * (1.0f/Ee);
    float var = sh[8] * (1.0f/Ee) - mu*mu;
    float inv = rsqrtf(var + LN_EPS);
    float4 gv = ((const float4*)gamma)[tid];
    float4 bv = ((const float4*)beta)[tid];
    float4 o;
    o.x = (v.x - mu)*inv*gv.x + bv.x;
    o.y = (v.y - mu)*inv*gv.y + bv.y;
    o.z = (v.z - mu)*inv*gv.z + bv.z;
    o.w = (v.w - mu)*inv*gv.w + bv.w;
    ((float4*)(y + (size_t)row * Ee))[tid] = o;
}

// ---------------- SGEMM: C[N][M] = A[N][K] @ W[K][M] (+bias, relu, +res) ----
// 128x128 tile, BK=8, 256 threads, 8x8 microtile per thread.
template<int RELU, int BIAS, int RES>
__global__ __launch_bounds__(256) void sgemm_kernel(
    const float* __restrict__ A, const float* __restrict__ W,
    const float* __restrict__ bias, const float* __restrict__ res,
    float* __restrict__ C, int K, int M)
{
    __shared__ float As[8][128];   // transposed A tile: As[k][row]
    __shared__ float Bs[8][128];   // W tile: Bs[k][col]
    int tid = threadIdx.x;
    int tx = tid & 15, ty = tid >> 4;
    int row0 = blockIdx.y * 128, col0 = blockIdx.x * 128;

    int arow = tid >> 1, aq = (tid & 1) * 4;    // A load: 128 rows x 8k as float4
    int bk   = tid >> 5, bc = (tid & 31) * 4;   // W load: 8k x 128 cols as float4
    const float* Ap = A + (size_t)(row0 + arow) * K + aq;
    const float* Wp = W + (size_t)bk * M + col0 + bc;

    float acc[8][8] = {};
    for (int k0 = 0; k0 < K; k0 += 8) {
        float4 av = *(const float4*)(Ap + k0);
        float4 bv = *(const float4*)(Wp + (size_t)k0 * M);
        As[aq + 0][arow] = av.x;
        As[aq + 1][arow] = av.y;
        As[aq + 2][arow] = av.z;
        As[aq + 3][arow] = av.w;
        *(float4*)&Bs[bk][bc] = bv;
        __syncthreads();
        #pragma unroll
        for (int kk = 0; kk < 8; kk++) {
            float4 a0 = *(const float4*)&As[kk][ty * 4];
            float4 a1 = *(const float4*)&As[kk][64 + ty * 4];
            float4 b0 = *(const float4*)&Bs[kk][tx * 4];
            float4 b1 = *(const float4*)&Bs[kk][64 + tx * 4];
            float a[8] = {a0.x,a0.y,a0.z,a0.w, a1.x,a1.y,a1.z,a1.w};
            float bb[8] = {b0.x,b0.y,b0.z,b0.w, b1.x,b1.y,b1.z,b1.w};
            #pragma unroll
            for (int i = 0; i < 8; i++)
                #pragma unroll
                for (int j = 0; j < 8; j++)
                    acc[i][j] += a[i] * bb[j];
        }
        __syncthreads();
    }

    #pragma unroll
    for (int i = 0; i < 8; i++) {
        int r = row0 + ((i < 4) ? ty * 4 + i : 64 + ty * 4 + (i - 4));
        #pragma unroll
        for (int j = 0; j < 8; j++) {
            int c = col0 + ((j < 4) ? tx * 4 + j : 64 + tx * 4 + (j - 4));
            float vv = acc[i][j];
            if (BIAS) vv += bias[c];
            if (RELU) vv = fmaxf(vv, 0.f);
            if (RES)  vv += res[(size_t)r * M + c];
            C[(size_t)r * M + c] = vv;
        }
    }
}

// ---------------- Flash attention (causal), BQ=BK=64, D=64, fp32 ------------
// grid (T/64, H, B), 256 threads (16x16, 4x4 microtile).
// 3x 16KB smem buffers (48KB exactly), XOR-swizzled for conflict-free access.
__global__ __launch_bounds__(256) void flash_kernel(
    const float* __restrict__ Q, const float* __restrict__ K,
    const float* __restrict__ V, float* __restrict__ O)
{
    __shared__ float Qs[64 * 64];  // [d][r] swizzled
    __shared__ float KV[64 * 64];  // K: [d][c] swizzled, then V: [c][d] swizzled
    __shared__ float Pt[64 * 64];  // [row][kcol]

    int qt = blockIdx.x, h = blockIdx.y, b = blockIdx.z;
    int tid = threadIdx.x;
    int tx = tid & 15, ty = tid >> 4;
    int qbase = qt * 64;
    const float scale = 0.125f;  // 1/sqrt(64)

    const float* Qg = Q + ((size_t)(b * Tt + qbase)) * Ee + h * Dd;
    #pragma unroll
    for (int it = 0; it < 16; it++) {
        int idx = tid + it * 256;
        int r = idx >> 6, d = idx & 63;
        Qs[d * 64 + (r ^ (d & 31))] = Qg[(size_t)r * Ee + d] * scale;
    }

    float accO[4][4] = {};
    float mrow[4] = {-INFINITY, -INFINITY, -INFINITY, -INFINITY};
    float lrow[4] = {};

    for (int kt = 0; kt <= qt; kt++) {
        const float* Kg = K + ((size_t)(b * Tt + kt * 64)) * Ee + h * Dd;
        #pragma unroll
        for (int it = 0; it < 16; it++) {
            int idx = tid + it * 256;
            int c = idx >> 6, d = idx & 63;
            KV[d * 64 + (c ^ (d & 31))] = Kg[(size_t)c * Ee + d];
        }
        __syncthreads();   // Q (first iter) + K visible

        float S[4][4] = {};
        #pragma unroll 8
        for (int kk = 0; kk < 64; kk++) {
            int sw = kk & 31;
            float qv[4], kv[4];
            #pragma unroll
            for (int i = 0; i < 4; i++) qv[i] = Qs[kk * 64 + ((4 * ty + i) ^ sw)];
            #pragma unroll
            for (int j = 0; j < 4; j++) kv[j] = KV[kk * 64 + ((4 * tx + j) ^ sw)];
            #pragma unroll
            for (int i = 0; i < 4; i++)
                #pragma unroll
                for (int j = 0; j < 4; j++)
                    S[i][j] += qv[i] * kv[j];
        }

        if (kt == qt) {
            #pragma unroll
            for (int i = 0; i < 4; i++)
                #pragma unroll
                for (int j = 0; j < 4; j++)
                    if (4 * tx + j > 4 * ty + i) S[i][j] = -INFINITY;
        }

        // online softmax per row (16 threads of a row = half-warp; shfl width 16)
        #pragma unroll
        for (int i = 0; i < 4; i++) {
            float mx = fmaxf(fmaxf(S[i][0], S[i][1]), fmaxf(S[i][2], S[i][3]));
            #pragma unroll
            for (int msk = 1; msk < 16; msk <<= 1)
                mx = fmaxf(mx, __shfl_xor_sync(0xffffffffu, mx, msk));
            float mnew = fmaxf(mrow[i], mx);
            float corr = __expf(mrow[i] - mnew);    // 0 on first tile (-inf)
            mrow[i] = mnew;
            float sum = 0.f;
            #pragma unroll
            for (int j = 0; j < 4; j++) {
                float p = __expf(S[i][j] - mnew);   // masked -> 0
                S[i][j] = p;
                sum += p;
            }
            #pragma unroll
            for (int msk = 1; msk < 16; msk <<= 1)
                sum += __shfl_xor_sync(0xffffffffu, sum, msk);
            lrow[i] = lrow[i] * corr + sum;
            #pragma unroll
            for (int j = 0; j < 4; j++) accO[i][j] *= corr;
            #pragma unroll
            for (int j = 0; j < 4; j++)
                Pt[(4 * ty + i) * 64 + 4 * tx + j] = S[i][j];
        }
        __syncthreads();   // Pt written; done reading K from KV

        const float* Vg = V + ((size_t)(b * Tt + kt * 64)) * Ee + h * Dd;
        #pragma unroll
        for (int it = 0; it < 16; it++) {
            int idx = tid + it * 256;
            int c = idx >> 6, d = idx & 63;
            KV[c * 64 + (d ^ (c & 31))] = Vg[(size_t)c * Ee + d];
        }
        __syncthreads();   // V visible

        #pragma unroll 8
        for (int c = 0; c < 64; c++) {
            int sw = c & 31;
            float pv[4], vv[4];
            #pragma unroll
            for (int i = 0; i < 4; i++) pv[i] = Pt[(4 * ty + i) * 64 + c];
            #pragma unroll
            for (int j = 0; j < 4; j++) vv[j] = KV[c * 64 + ((4 * tx + j) ^ sw)];
            #pragma unroll
            for (int i = 0; i < 4; i++)
                #pragma unroll
                for (int j = 0; j < 4; j++)
                    accO[i][j] += pv[i] * vv[j];
        }
        __syncthreads();   // before next tile overwrites KV/Pt
    }

    float* Og = O + ((size_t)(b * Tt + qbase)) * Ee + h * Dd;
    #pragma unroll
    for (int i = 0; i < 4; i++) {
        float inv = 1.f / lrow[i];
        #pragma unroll
        for (int j = 0; j < 4; j++)
            Og[(size_t)(4 * ty + i) * Ee + 4 * tx + j] = accO[i][j] * inv;
    }
}

// ---------------- orchestration ---------------------------------------------
extern "C" void kernel_launch(void* const* d_in, const int* in_sizes, int n_in,
                              void* d_out, int out_size)
{
    (void)in_sizes; (void)n_in; (void)out_size;
    const float* x     = (const float*)d_in[0];
    const float* ln1_g = (const float*)d_in[1];
    const float* ln1_b = (const float*)d_in[2];
    const float* Wq    = (const float*)d_in[3];
    const float* Wk    = (const float*)d_in[4];
    const float* Wv    = (const float*)d_in[5];
    const float* Wo    = (const float*)d_in[6];
    const float* bo    = (const float*)d_in[7];
    const float* ln2_g = (const float*)d_in[8];
    const float* ln2_b = (const float*)d_in[9];
    const float* W1    = (const float*)d_in[10];
    const float* b1    = (const float*)d_in[11];
    const float* W2    = (const float*)d_in[12];
    const float* b2    = (const float*)d_in[13];
    float* out = (float*)d_out;

    float *xn, *q, *k, *v, *att, *x1, *h, *ff;
    cudaGetSymbolAddress((void**)&xn,  g_xn);
    cudaGetSymbolAddress((void**)&q,   g_q);
    cudaGetSymbolAddress((void**)&k,   g_k);
    cudaGetSymbolAddress((void**)&v,   g_v);
    cudaGetSymbolAddress((void**)&att, g_att);
    cudaGetSymbolAddress((void**)&x1,  g_x1);
    cudaGetSymbolAddress((void**)&h,   g_h);
    cudaGetSymbolAddress((void**)&ff,  g_ff);

    dim3 gE(Ee / 128, Nn / 128);       // 8 x 32
    dim3 gF(FF / 128, Nn / 128);       // 32 x 32

    // 1) xn = LN1(x)
    ln_kernel<<<Nn, 256>>>(x, ln1_g, ln1_b, xn);
    // 2-4) q/k/v = xn @ W{q,k,v}
    sgemm_kernel<0,0,0><<<gE, 256>>>(xn, Wq, nullptr, nullptr, q, Ee, Ee);
    sgemm_kernel<0,0,0><<<gE, 256>>>(xn, Wk, nullptr, nullptr, k, Ee, Ee);
    sgemm_kernel<0,0,0><<<gE, 256>>>(xn, Wv, nullptr, nullptr, v, Ee, Ee);
    // 5) att = causal flash attention
    flash_kernel<<<dim3(Tt / 64, Hh, Bb), 256>>>(q, k, v, att);
    // 6) x1 = x + att @ Wo + bo
    sgemm_kernel<0,1,1><<<gE, 256>>>(att, Wo, bo, x, x1, Ee, Ee);
    // 7) h = LN2(x1)
    ln_kernel<<<Nn, 256>>>(x1, ln2_g, ln2_b, h);
    // 8) ff = relu(h @ W1 + b1)
    sgemm_kernel<1,1,0><<<gF, 256>>>(h, W1, b1, nullptr, ff, Ee, FF);
    // 9) out = x1 + ff @ W2 + b2
    sgemm_kernel<0,1,1><<<gE, 256>>>(ff, W2, b2, x1, out, FF, Ee);
}

// round 10
// speedup vs baseline: 1.5795x; 1.5795x over previous
#include <cuda_runtime.h>
#include <cuda_bf16.h>
#include <cstdint>
#include <math.h>

#define Bb 2
#define Tt 2048
#define Ee 1024
#define Hh 16
#define Dd 64
#define Nn (Bb*Tt)      /* 4096 rows */
#define FF 4096
#define LN_EPS 1e-5f

// ======================= scratch (__device__ globals) =======================
__device__ float g_xn[Nn*Ee];
__device__ float g_q [Nn*Ee];
__device__ float g_k [Nn*Ee];
__device__ float g_v [Nn*Ee];
__device__ float g_att[Nn*Ee];
__device__ float g_x1[Nn*Ee];
__device__ float g_h [Nn*Ee];
__device__ float g_ff[(size_t)Nn*FF];

// bf16 split weights, transposed to [M_out][K] (K-major rows)
__device__ __nv_bfloat16 g_wqh[Ee*Ee], g_wql[Ee*Ee];
__device__ __nv_bfloat16 g_wkh[Ee*Ee], g_wkl[Ee*Ee];
__device__ __nv_bfloat16 g_wvh[Ee*Ee], g_wvl[Ee*Ee];
__device__ __nv_bfloat16 g_woh[Ee*Ee], g_wol[Ee*Ee];
__device__ __nv_bfloat16 g_w1h[(size_t)Ee*FF], g_w1l[(size_t)Ee*FF];
__device__ __nv_bfloat16 g_w2h[(size_t)FF*Ee], g_w2l[(size_t)FF*Ee];
// bf16 split activations (reused per GEMM; sized for the largest: [Nn][FF])
__device__ __nv_bfloat16 g_ah[(size_t)Nn*FF], g_al[(size_t)Nn*FF];

// ======================= PTX helpers (baseline compute_103 only) ============
__device__ __forceinline__ uint32_t smem_to_u32(const void* p) {
    uint32_t a;
    asm("{ .reg .u64 t; cvta.to.shared.u64 t, %1; cvt.u32.u64 %0, t; }"
        : "=r"(a) : "l"(p));
    return a;
}
__device__ __forceinline__ void cp_async16(uint32_t dst, const void* src) {
    asm volatile("cp.async.cg.shared.global [%0], [%1], 16;"
                 :: "r"(dst), "l"(src) : "memory");
}
#define CP_COMMIT() asm volatile("cp.async.commit_group;" ::: "memory")
#define CP_WAIT(n)  asm volatile("cp.async.wait_group %0;" :: "n"(n) : "memory")

__device__ __forceinline__ void ldmx4(uint32_t& r0, uint32_t& r1,
                                      uint32_t& r2, uint32_t& r3, uint32_t a) {
    asm volatile("ldmatrix.sync.aligned.m8n8.x4.shared.b16 {%0,%1,%2,%3}, [%4];"
                 : "=r"(r0), "=r"(r1), "=r"(r2), "=r"(r3) : "r"(a));
}
__device__ __forceinline__ void mma16816(float* c, uint32_t a0, uint32_t a1,
                                         uint32_t a2, uint32_t a3,
                                         uint32_t b0, uint32_t b1) {
    asm volatile(
        "mma.sync.aligned.m16n8k16.row.col.f32.bf16.bf16.f32 "
        "{%0,%1,%2,%3}, {%4,%5,%6,%7}, {%8,%9}, {%0,%1,%2,%3};"
        : "+f"(c[0]), "+f"(c[1]), "+f"(c[2]), "+f"(c[3])
        : "r"(a0), "r"(a1), "r"(a2), "r"(a3), "r"(b0), "r"(b1));
}

// ======================= LayerNorm ==========================================
__global__ __launch_bounds__(256) void ln_kernel(
    const float* __restrict__ x, const float* __restrict__ gamma,
    const float* __restrict__ beta, float* __restrict__ y)
{
    int row = blockIdx.x;
    int tid = threadIdx.x;
    const float4* xp = (const float4*)(x + (size_t)row * Ee);
    float4 v = xp[tid];
    float s  = v.x + v.y + v.z + v.w;
    float sq = v.x*v.x + v.y*v.y + v.z*v.z + v.w*v.w;
    #pragma unroll
    for (int m = 16; m >= 1; m >>= 1) {
        s  += __shfl_xor_sync(0xffffffffu, s,  m);
        sq += __shfl_xor_sync(0xffffffffu, sq, m);
    }
    __shared__ float sh[16];
    int w = tid >> 5, l = tid & 31;
    if (l == 0) { sh[w] = s; sh[8 + w] = sq; }
    __syncthreads();
    if (tid < 32) {
        s  = (l < 8) ? sh[l]     : 0.f;
        sq = (l < 8) ? sh[8 + l] : 0.f;
        #pragma unroll
        for (int m = 4; m >= 1; m >>= 1) {
            s  += __shfl_xor_sync(0xffffffffu, s,  m);
            sq += __shfl_xor_sync(0xffffffffu, sq, m);
        }
        if (l == 0) { sh[0] = s; sh[8] = sq; }
    }
    __syncthreads();
    float mu  = sh[0] * (1.0f/Ee);
    float var = sh[8] * (1.0f/Ee) - mu*mu;
    float inv = rsqrtf(var + LN_EPS);
    float4 gv = ((const float4*)gamma)[tid];
    float4 bv = ((const float4*)beta)[tid];
    float4 o;
    o.x = (v.x - mu)*inv*gv.x + bv.x;
    o.y = (v.y - mu)*inv*gv.y + bv.y;
    o.z = (v.z - mu)*inv*gv.z + bv.z;
    o.w = (v.w - mu)*inv*gv.w + bv.w;
    ((float4*)(y + (size_t)row * Ee))[tid] = o;
}

// ============== f32 -> split-bf16 (hi/lo) elementwise conversion ============
__global__ __launch_bounds__(256) void conv_hl_kernel(
    const float* __restrict__ in, __nv_bfloat16* __restrict__ hi,
    __nv_bfloat16* __restrict__ lo)
{
    size_t i = ((size_t)blockIdx.x * 256 + threadIdx.x) * 4;
    float4 v = *(const float4*)(in + i);
    float f[4] = {v.x, v.y, v.z, v.w};
    __nv_bfloat16 hv[4], lv[4];
    #pragma unroll
    for (int j = 0; j < 4; j++) {
        hv[j] = __float2bfloat16(f[j]);
        lv[j] = __float2bfloat16(f[j] - __bfloat162float(hv[j]));
    }
    *(uint2*)(hi + i) = *(const uint2*)hv;
    *(uint2*)(lo + i) = *(const uint2*)lv;
}

// ====== W[K][M] f32 -> Wt_hi/lo[M][K] bf16 (transpose + split convert) ======
__global__ __launch_bounds__(256) void convT_hl_kernel(
    const float* __restrict__ W, __nv_bfloat16* __restrict__ th,
    __nv_bfloat16* __restrict__ tl, int K, int M)
{
    __shared__ float t[32][33];
    int m0 = blockIdx.x * 32, k0 = blockIdx.y * 32;
    int tx = threadIdx.x, ty = threadIdx.y;   // (32, 8)
    #pragma unroll
    for (int j = 0; j < 4; j++)
        t[ty + j*8][tx] = W[(size_t)(k0 + ty + j*8) * M + m0 + tx];
    __syncthreads();
    #pragma unroll
    for (int j = 0; j < 4; j++) {
        int ml = ty + j*8;
        float f = t[tx][ml];
        __nv_bfloat16 hv = __float2bfloat16(f);
        __nv_bfloat16 lv = __float2bfloat16(f - __bfloat162float(hv));
        size_t o = (size_t)(m0 + ml) * K + k0 + tx;
        th[o] = hv;
        tl[o] = lv;
    }
}

// ======================= HMMA split-bf16 GEMM ===============================
// C[N][M] = A[N][K] @ W[K][M]; A hi/lo bf16 [N][K], W hi/lo bf16 [M][K].
// 128x128x32 block tile, 256 thr (8 warps, 2x4 of 64x32), 2-stage cp.async.
// D = Ah*Bh + Ah*Bl + Al*Bh in fp32 acc via mma.sync.m16n8k16.
// smem row stride 80B (5 x 16B, conflict-free ldmatrix).
#define T_AH 0
#define T_AL 10240
#define T_BH 20480
#define T_BL 30720
#define STAGE_B 40960
#define HG_SMEM (2 * STAGE_B)

template<int RELU, int BIAS, int RES>
__global__ __launch_bounds__(256, 1) void hgemm_kernel(
    const __nv_bfloat16* __restrict__ Ah, const __nv_bfloat16* __restrict__ Al,
    const __nv_bfloat16* __restrict__ Bh, const __nv_bfloat16* __restrict__ Bl,
    const float* __restrict__ bias, const float* __restrict__ res,
    float* __restrict__ C, int K, int M)
{
    extern __shared__ char smem[];
    const uint32_t sb = smem_to_u32(smem);
    const int tid = threadIdx.x;
    const int wid = tid >> 5, lid = tid & 31;
    const int wr = wid >> 2, wc = wid & 3;      // warp tile: rows wr*64, cols wc*32
    const int row0 = blockIdx.y * 128, col0 = blockIdx.x * 128;

    const __nv_bfloat16* src[4] = {
        Ah + (size_t)row0 * K, Al + (size_t)row0 * K,
        Bh + (size_t)col0 * K, Bl + (size_t)col0 * K };

    // per-thread cp.async coords: 2 units/tile (128 rows x 4 segs of 16B)
    const int ldr0 = tid >> 2, ldseg = (tid & 3);
    // ldmatrix lane offsets (A: 16 rows x 2 k-halves; B: same on n)
    const uint32_t mrow = (uint32_t)(lid & 15);
    const uint32_t mcol = (uint32_t)(lid >> 4);
    const uint32_t aLane = (uint32_t)((wr * 64 + mrow) * 80 + mcol * 16);
    const uint32_t bLane = (uint32_t)((wc * 32 + mrow) * 80 + mcol * 16);

    float acc[4][4][4] = {};
    const int nchunk = K >> 5;

    auto issue = [&](int c, int stg) {
        const size_t k0 = (size_t)c * 32;
        #pragma unroll
        for (int t = 0; t < 4; t++) {
            const __nv_bfloat16* s = src[t] + k0;
            uint32_t dst = sb + stg * STAGE_B + t * 10240;
            #pragma unroll
            for (int i = 0; i < 2; i++) {
                int r = ldr0 + i * 64;
                cp_async16(dst + (uint32_t)(r * 80 + ldseg * 16),
                           s + (size_t)r * K + ldseg * 8);
            }
        }
        CP_COMMIT();
    };

    issue(0, 0);
    for (int c = 0; c < nchunk; c++) {
        if (c + 1 < nchunk) {
            issue(c + 1, (c + 1) & 1);
            CP_WAIT(1);
        } else {
            CP_WAIT(0);
        }
        __syncthreads();

        const uint32_t st = sb + (uint32_t)((c & 1) * STAGE_B);
        #pragma unroll
        for (int kk = 0; kk < 2; kk++) {
            const uint32_t ko = (uint32_t)(kk * 32);   // 16 bf16 = 32B
            uint32_t ah[4][4], al[4][4], bh[2][4], bl[2][4];
            #pragma unroll
            for (int mi = 0; mi < 4; mi++) {
                ldmx4(ah[mi][0], ah[mi][1], ah[mi][2], ah[mi][3],
                      st + T_AH + aLane + (uint32_t)(mi * 1280) + ko);
                ldmx4(al[mi][0], al[mi][1], al[mi][2], al[mi][3],
                      st + T_AL + aLane + (uint32_t)(mi * 1280) + ko);
            }
            #pragma unroll
            for (int np = 0; np < 2; np++) {
                ldmx4(bh[np][0], bh[np][1], bh[np][2], bh[np][3],
                      st + T_BH + bLane + (uint32_t)(np * 1280) + ko);
                ldmx4(bl[np][0], bl[np][1], bl[np][2], bl[np][3],
                      st + T_BL + bLane + (uint32_t)(np * 1280) + ko);
            }
            #pragma unroll
            for (int mi = 0; mi < 4; mi++) {
                #pragma unroll
                for (int nj = 0; nj < 4; nj++) {
                    uint32_t h0 = bh[nj >> 1][nj & 1], h1 = bh[nj >> 1][(nj & 1) + 2];
                    uint32_t l0 = bl[nj >> 1][nj & 1], l1 = bl[nj >> 1][(nj & 1) + 2];
                    float* cc = acc[mi][nj];
                    mma16816(cc, ah[mi][0], ah[mi][1], ah[mi][2], ah[mi][3], h0, h1);
                    mma16816(cc, ah[mi][0], ah[mi][1], ah[mi][2], ah[mi][3], l0, l1);
                    mma16816(cc, al[mi][0], al[mi][1], al[mi][2], al[mi][3], h0, h1);
                }
            }
        }
        __syncthreads();
    }

    // epilogue
    const int l4 = lid >> 2, l2 = (lid & 3) * 2;
    #pragma unroll
    for (int mi = 0; mi < 4; mi++) {
        const int r = row0 + wr * 64 + mi * 16 + l4;
        #pragma unroll
        for (int nj = 0; nj < 4; nj++) {
            const int cgl = col0 + wc * 32 + nj * 8 + l2;
            float b0 = 0.f, b1 = 0.f;
            if (BIAS) { b0 = bias[cgl]; b1 = bias[cgl + 1]; }
            float v0 = acc[mi][nj][0] + b0, v1 = acc[mi][nj][1] + b1;
            float v2 = acc[mi][nj][2] + b0, v3 = acc[mi][nj][3] + b1;
            if (RELU) {
                v0 = fmaxf(v0, 0.f); v1 = fmaxf(v1, 0.f);
                v2 = fmaxf(v2, 0.f); v3 = fmaxf(v3, 0.f);
            }
            if (RES) {
                const float* r0p = res + (size_t)r * M + cgl;
                const float* r1p = res + (size_t)(r + 8) * M + cgl;
                v0 += r0p[0]; v1 += r0p[1];
                v2 += r1p[0]; v3 += r1p[1];
            }
            float2 o0 = {v0, v1}, o1 = {v2, v3};
            *(float2*)(C + (size_t)r * M + cgl) = o0;
            *(float2*)(C + (size_t)(r + 8) * M + cgl) = o1;
        }
    }
}

// ======================= Flash attention (fp32) =============================
__global__ __launch_bounds__(256) void flash_kernel(
    const float* __restrict__ Q, const float* __restrict__ K,
    const float* __restrict__ V, float* __restrict__ O)
{
    __shared__ float Qs[64 * 64];
    __shared__ float KV[64 * 64];
    __shared__ float Pt[64 * 64];

    int qt = blockIdx.x, h = blockIdx.y, b = blockIdx.z;
    int tid = threadIdx.x;
    int tx = tid & 15, ty = tid >> 4;
    int qbase = qt * 64;
    const float scale = 0.125f;

    const float* Qg = Q + ((size_t)(b * Tt + qbase)) * Ee + h * Dd;
    #pragma unroll
    for (int it = 0; it < 16; it++) {
        int idx = tid + it * 256;
        int r = idx >> 6, d = idx & 63;
        Qs[d * 64 + (r ^ (d & 31))] = Qg[(size_t)r * Ee + d] * scale;
    }

    float accO[4][4] = {};
    float mrow[4] = {-INFINITY, -INFINITY, -INFINITY, -INFINITY};
    float lrow[4] = {};

    for (int kt = 0; kt <= qt; kt++) {
        const float* Kg = K + ((size_t)(b * Tt + kt * 64)) * Ee + h * Dd;
        #pragma unroll
        for (int it = 0; it < 16; it++) {
            int idx = tid + it * 256;
            int c = idx >> 6, d = idx & 63;
            KV[d * 64 + (c ^ (d & 31))] = Kg[(size_t)c * Ee + d];
        }
        __syncthreads();

        float S[4][4] = {};
        #pragma unroll 8
        for (int kk = 0; kk < 64; kk++) {
            int sw = kk & 31;
            float qv[4], kv[4];
            #pragma unroll
            for (int i = 0; i < 4; i++) qv[i] = Qs[kk * 64 + ((4 * ty + i) ^ sw)];
            #pragma unroll
            for (int j = 0; j < 4; j++) kv[j] = KV[kk * 64 + ((4 * tx + j) ^ sw)];
            #pragma unroll
            for (int i = 0; i < 4; i++)
                #pragma unroll
                for (int j = 0; j < 4; j++)
                    S[i][j] += qv[i] * kv[j];
        }

        if (kt == qt) {
            #pragma unroll
            for (int i = 0; i < 4; i++)
                #pragma unroll
                for (int j = 0; j < 4; j++)
                    if (4 * tx + j > 4 * ty + i) S[i][j] = -INFINITY;
        }

        #pragma unroll
        for (int i = 0; i < 4; i++) {
            float mx = fmaxf(fmaxf(S[i][0], S[i][1]), fmaxf(S[i][2], S[i][3]));
            #pragma unroll
            for (int msk = 1; msk < 16; msk <<= 1)
                mx = fmaxf(mx, __shfl_xor_sync(0xffffffffu, mx, msk));
            float mnew = fmaxf(mrow[i], mx);
            float corr = __expf(mrow[i] - mnew);
            mrow[i] = mnew;
            float sum = 0.f;
            #pragma unroll
            for (int j = 0; j < 4; j++) {
                float p = __expf(S[i][j] - mnew);
                S[i][j] = p;
                sum += p;
            }
            #pragma unroll
            for (int msk = 1; msk < 16; msk <<= 1)
                sum += __shfl_xor_sync(0xffffffffu, sum, msk);
            lrow[i] = lrow[i] * corr + sum;
            #pragma unroll
            for (int j = 0; j < 4; j++) accO[i][j] *= corr;
            #pragma unroll
            for (int j = 0; j < 4; j++)
                Pt[(4 * ty + i) * 64 + 4 * tx + j] = S[i][j];
        }
        __syncthreads();

        const float* Vg = V + ((size_t)(b * Tt + kt * 64)) * Ee + h * Dd;
        #pragma unroll
        for (int it = 0; it < 16; it++) {
            int idx = tid + it * 256;
            int c = idx >> 6, d = idx & 63;
            KV[c * 64 + (d ^ (c & 31))] = Vg[(size_t)c * Ee + d];
        }
        __syncthreads();

        #pragma unroll 8
        for (int c = 0; c < 64; c++) {
            int sw = c & 31;
            float pv[4], vv[4];
            #pragma unroll
            for (int i = 0; i < 4; i++) pv[i] = Pt[(4 * ty + i) * 64 + c];
            #pragma unroll
            for (int j = 0; j < 4; j++) vv[j] = KV[c * 64 + ((4 * tx + j) ^ sw)];
            #pragma unroll
            for (int i = 0; i < 4; i++)
                #pragma unroll
                for (int j = 0; j < 4; j++)
                    accO[i][j] += pv[i] * vv[j];
        }
        __syncthreads();
    }

    float* Og = O + ((size_t)(b * Tt + qbase)) * Ee + h * Dd;
    #pragma unroll
    for (int i = 0; i < 4; i++) {
        float inv = 1.f / lrow[i];
        #pragma unroll
        for (int j = 0; j < 4; j++)
            Og[(size_t)(4 * ty + i) * Ee + 4 * tx + j] = accO[i][j] * inv;
    }
}

// ======================= orchestration ======================================
extern "C" void kernel_launch(void* const* d_in, const int* in_sizes, int n_in,
                              void* d_out, int out_size)
{
    (void)in_sizes; (void)n_in; (void)out_size;
    const float* x     = (const float*)d_in[0];
    const float* ln1_g = (const float*)d_in[1];
    const float* ln1_b = (const float*)d_in[2];
    const float* Wq    = (const float*)d_in[3];
    const float* Wk    = (const float*)d_in[4];
    const float* Wv    = (const float*)d_in[5];
    const float* Wo    = (const float*)d_in[6];
    const float* bo    = (const float*)d_in[7];
    const float* ln2_g = (const float*)d_in[8];
    const float* ln2_b = (const float*)d_in[9];
    const float* W1    = (const float*)d_in[10];
    const float* b1    = (const float*)d_in[11];
    const float* W2    = (const float*)d_in[12];
    const float* b2    = (const float*)d_in[13];
    float* out = (float*)d_out;

    float *xn, *q, *k, *v, *att, *x1, *h, *ff;
    cudaGetSymbolAddress((void**)&xn,  g_xn);
    cudaGetSymbolAddress((void**)&q,   g_q);
    cudaGetSymbolAddress((void**)&k,   g_k);
    cudaGetSymbolAddress((void**)&v,   g_v);
    cudaGetSymbolAddress((void**)&att, g_att);
    cudaGetSymbolAddress((void**)&x1,  g_x1);
    cudaGetSymbolAddress((void**)&h,   g_h);
    cudaGetSymbolAddress((void**)&ff,  g_ff);

    __nv_bfloat16 *wqh,*wql,*wkh,*wkl,*wvh,*wvl,*woh,*wol,*w1h,*w1l,*w2h,*w2l,*ah,*al;
    cudaGetSymbolAddress((void**)&wqh, g_wqh); cudaGetSymbolAddress((void**)&wql, g_wql);
    cudaGetSymbolAddress((void**)&wkh, g_wkh); cudaGetSymbolAddress((void**)&wkl, g_wkl);
    cudaGetSymbolAddress((void**)&wvh, g_wvh); cudaGetSymbolAddress((void**)&wvl, g_wvl);
    cudaGetSymbolAddress((void**)&woh, g_woh); cudaGetSymbolAddress((void**)&wol, g_wol);
    cudaGetSymbolAddress((void**)&w1h, g_w1h); cudaGetSymbolAddress((void**)&w1l, g_w1l);
    cudaGetSymbolAddress((void**)&w2h, g_w2h); cudaGetSymbolAddress((void**)&w2l, g_w2l);
    cudaGetSymbolAddress((void**)&ah,  g_ah);  cudaGetSymbolAddress((void**)&al,  g_al);

    cudaFuncSetAttribute(hgemm_kernel<0,0,0>, cudaFuncAttributeMaxDynamicSharedMemorySize, HG_SMEM);
    cudaFuncSetAttribute(hgemm_kernel<0,1,1>, cudaFuncAttributeMaxDynamicSharedMemorySize, HG_SMEM);
    cudaFuncSetAttribute(hgemm_kernel<1,1,0>, cudaFuncAttributeMaxDynamicSharedMemorySize, HG_SMEM);

    dim3 tb(32, 8);
    dim3 gE(8, 32);     // 1024-out GEMMs over 4096 rows
    dim3 gF(32, 32);    // 4096-out GEMM

    // weight conversions (transpose + split to bf16 hi/lo)
    convT_hl_kernel<<<dim3(32, 32),  tb>>>(Wq, wqh, wql, Ee, Ee);
    convT_hl_kernel<<<dim3(32, 32),  tb>>>(Wk, wkh, wkl, Ee, Ee);
    convT_hl_kernel<<<dim3(32, 32),  tb>>>(Wv, wvh, wvl, Ee, Ee);
    convT_hl_kernel<<<dim3(32, 32),  tb>>>(Wo, woh, wol, Ee, Ee);
    convT_hl_kernel<<<dim3(128, 32), tb>>>(W1, w1h, w1l, Ee, FF);
    convT_hl_kernel<<<dim3(32, 128), tb>>>(W2, w2h, w2l, FF, Ee);

    // 1) xn = LN1(x); split to bf16
    ln_kernel<<<Nn, 256>>>(x, ln1_g, ln1_b, xn);
    conv_hl_kernel<<<(Nn*Ee)/1024, 256>>>(xn, ah, al);
    // 2-4) q/k/v
    hgemm_kernel<0,0,0><<<gE, 256, HG_SMEM>>>(ah, al, wqh, wql, nullptr, nullptr, q, Ee, Ee);
    hgemm_kernel<0,0,0><<<gE, 256, HG_SMEM>>>(ah, al, wkh, wkl, nullptr, nullptr, k, Ee, Ee);
    hgemm_kernel<0,0,0><<<gE, 256, HG_SMEM>>>(ah, al, wvh, wvl, nullptr, nullptr, v, Ee, Ee);
    // 5) attention
    flash_kernel<<<dim3(Tt / 64, Hh, Bb), 256>>>(q, k, v, att);
    // 6) x1 = x + att @ Wo + bo
    conv_hl_kernel<<<(Nn*Ee)/1024, 256>>>(att, ah, al);
    hgemm_kernel<0,1,1><<<gE, 256, HG_SMEM>>>(ah, al, woh, wol, bo, x, x1, Ee, Ee);
    // 7) h = LN2(x1)
    ln_kernel<<<Nn, 256>>>(x1, ln2_g, ln2_b, h);
    // 8) ff = relu(h @ W1 + b1)
    conv_hl_kernel<<<(Nn*Ee)/1024, 256>>>(h, ah, al);
    hgemm_kernel<1,1,0><<<gF, 256, HG_SMEM>>>(ah, al, w1h, w1l, b1, nullptr, ff, Ee, FF);
    // 9) out = x1 + ff @ W2 + b2
    conv_hl_kernel<<<((size_t)Nn*FF)/1024, 256>>>(ff, ah, al);
    hgemm_kernel<0,1,1><<<gE, 256, HG_SMEM>>>(ah, al, w2h, w2l, b2, x1, out, FF, Ee);
}

// round 11
// speedup vs baseline: 2.3143x; 1.4652x over previous
#include <cuda_runtime.h>
#include <cuda_bf16.h>
#include <cstdint>
#include <math.h>

#define Bb 2
#define Tt 2048
#define Ee 1024
#define Hh 16
#define Dd 64
#define Nn (Bb*Tt)      /* 4096 rows */
#define FF 4096
#define LN_EPS 1e-5f

// ======================= scratch (__device__ globals) =======================
__device__ float g_x1[Nn*Ee];

// bf16 split weights, transposed to [M_out][K] (K-major rows)
__device__ __nv_bfloat16 g_wqh[Ee*Ee], g_wql[Ee*Ee];
__device__ __nv_bfloat16 g_wkh[Ee*Ee], g_wkl[Ee*Ee];
__device__ __nv_bfloat16 g_wvh[Ee*Ee], g_wvl[Ee*Ee];
__device__ __nv_bfloat16 g_woh[Ee*Ee], g_wol[Ee*Ee];
__device__ __nv_bfloat16 g_w1h[(size_t)Ee*FF], g_w1l[(size_t)Ee*FF];
__device__ __nv_bfloat16 g_w2h[(size_t)FF*Ee], g_w2l[(size_t)FF*Ee];
// bf16 split activations
__device__ __nv_bfloat16 g_ah[(size_t)Nn*FF], g_al[(size_t)Nn*FF]; // LN1 out, later FF out
__device__ __nv_bfloat16 g_qh[Nn*Ee],  g_ql[Nn*Ee];
__device__ __nv_bfloat16 g_kh[Nn*Ee],  g_kl[Nn*Ee];
__device__ __nv_bfloat16 g_vh[Nn*Ee],  g_vl[Nn*Ee];
__device__ __nv_bfloat16 g_vth[Nn*Ee], g_vtl[Nn*Ee];   // V^T: [b,h][d][t]
__device__ __nv_bfloat16 g_atth[Nn*Ee], g_attl[Nn*Ee];
__device__ __nv_bfloat16 g_hh[Nn*Ee],  g_hl[Nn*Ee];    // LN2 out

// ======================= PTX helpers (baseline compute_103 only) ============
__device__ __forceinline__ uint32_t smem_to_u32(const void* p) {
    uint32_t a;
    asm("{ .reg .u64 t; cvta.to.shared.u64 t, %1; cvt.u32.u64 %0, t; }"
        : "=r"(a) : "l"(p));
    return a;
}
__device__ __forceinline__ void cp_async16(uint32_t dst, const void* src) {
    asm volatile("cp.async.cg.shared.global [%0], [%1], 16;"
                 :: "r"(dst), "l"(src) : "memory");
}
#define CP_COMMIT() asm volatile("cp.async.commit_group;" ::: "memory")
#define CP_WAIT(n)  asm volatile("cp.async.wait_group %0;" :: "n"(n) : "memory")

__device__ __forceinline__ void ldmx4(uint32_t& r0, uint32_t& r1,
                                      uint32_t& r2, uint32_t& r3, uint32_t a) {
    asm volatile("ldmatrix.sync.aligned.m8n8.x4.shared.b16 {%0,%1,%2,%3}, [%4];"
                 : "=r"(r0), "=r"(r1), "=r"(r2), "=r"(r3) : "r"(a));
}
__device__ __forceinline__ void mma16816(float* c, uint32_t a0, uint32_t a1,
                                         uint32_t a2, uint32_t a3,
                                         uint32_t b0, uint32_t b1) {
    asm volatile(
        "mma.sync.aligned.m16n8k16.row.col.f32.bf16.bf16.f32 "
        "{%0,%1,%2,%3}, {%4,%5,%6,%7}, {%8,%9}, {%0,%1,%2,%3};"
        : "+f"(c[0]), "+f"(c[1]), "+f"(c[2]), "+f"(c[3])
        : "r"(a0), "r"(a1), "r"(a2), "r"(a3), "r"(b0), "r"(b1));
}
__device__ __forceinline__ uint32_t pk2(float a, float b) {
    __nv_bfloat16 ha = __float2bfloat16(a), hb = __float2bfloat16(b);
    uint16_t ua = *(uint16_t*)&ha, ub = *(uint16_t*)&hb;
    return (uint32_t)ua | ((uint32_t)ub << 16);
}
__device__ __forceinline__ float blo(float a) {  // residual after bf16 round
    __nv_bfloat16 h = __float2bfloat16(a);
    return a - __bfloat162float(h);
}

// ======================= LayerNorm -> bf16 hi/lo ============================
__global__ __launch_bounds__(256) void ln_hl_kernel(
    const float* __restrict__ x, const float* __restrict__ gamma,
    const float* __restrict__ beta, __nv_bfloat16* __restrict__ hi,
    __nv_bfloat16* __restrict__ lo)
{
    int row = blockIdx.x;
    int tid = threadIdx.x;
    const float4* xp = (const float4*)(x + (size_t)row * Ee);
    float4 v = xp[tid];
    float s  = v.x + v.y + v.z + v.w;
    float sq = v.x*v.x + v.y*v.y + v.z*v.z + v.w*v.w;
    #pragma unroll
    for (int m = 16; m >= 1; m >>= 1) {
        s  += __shfl_xor_sync(0xffffffffu, s,  m);
        sq += __shfl_xor_sync(0xffffffffu, sq, m);
    }
    __shared__ float sh[16];
    int w = tid >> 5, l = tid & 31;
    if (l == 0) { sh[w] = s; sh[8 + w] = sq; }
    __syncthreads();
    if (tid < 32) {
        s  = (l < 8) ? sh[l]     : 0.f;
        sq = (l < 8) ? sh[8 + l] : 0.f;
        #pragma unroll
        for (int m = 4; m >= 1; m >>= 1) {
            s  += __shfl_xor_sync(0xffffffffu, s,  m);
            sq += __shfl_xor_sync(0xffffffffu, sq, m);
        }
        if (l == 0) { sh[0] = s; sh[8] = sq; }
    }
    __syncthreads();
    float mu  = sh[0] * (1.0f/Ee);
    float var = sh[8] * (1.0f/Ee) - mu*mu;
    float inv = rsqrtf(var + LN_EPS);
    float4 gv = ((const float4*)gamma)[tid];
    float4 bv = ((const float4*)beta)[tid];
    float f[4];
    f[0] = (v.x - mu)*inv*gv.x + bv.x;
    f[1] = (v.y - mu)*inv*gv.y + bv.y;
    f[2] = (v.z - mu)*inv*gv.z + bv.z;
    f[3] = (v.w - mu)*inv*gv.w + bv.w;
    __nv_bfloat16 hv[4], lv[4];
    #pragma unroll
    for (int j = 0; j < 4; j++) {
        hv[j] = __float2bfloat16(f[j]);
        lv[j] = __float2bfloat16(f[j] - __bfloat162float(hv[j]));
    }
    size_t o = (size_t)row * Ee + tid * 4;
    *(uint2*)(hi + o) = *(const uint2*)hv;
    *(uint2*)(lo + o) = *(const uint2*)lv;
}

// ====== W[K][M] f32 -> Wt_hi/lo[M][K] bf16 (transpose + split, scaled) ======
__global__ __launch_bounds__(256) void convT_hl_kernel(
    const float* __restrict__ W, __nv_bfloat16* __restrict__ th,
    __nv_bfloat16* __restrict__ tl, int K, int M, float scale)
{
    __shared__ float t[32][33];
    int m0 = blockIdx.x * 32, k0 = blockIdx.y * 32;
    int tx = threadIdx.x, ty = threadIdx.y;   // (32, 8)
    #pragma unroll
    for (int j = 0; j < 4; j++)
        t[ty + j*8][tx] = W[(size_t)(k0 + ty + j*8) * M + m0 + tx];
    __syncthreads();
    #pragma unroll
    for (int j = 0; j < 4; j++) {
        int ml = ty + j*8;
        float f = t[tx][ml] * scale;
        __nv_bfloat16 hv = __float2bfloat16(f);
        __nv_bfloat16 lv = __float2bfloat16(f - __bfloat162float(hv));
        size_t o = (size_t)(m0 + ml) * K + k0 + tx;
        th[o] = hv;
        tl[o] = lv;
    }
}

// ====== V [t][E] hi/lo -> V^T [b,h][d][t] hi/lo =============================
__global__ __launch_bounds__(256) void vtrans_kernel(
    const __nv_bfloat16* __restrict__ vh, const __nv_bfloat16* __restrict__ vl,
    __nv_bfloat16* __restrict__ vth, __nv_bfloat16* __restrict__ vtl)
{
    __shared__ __nv_bfloat16 s[64][72];
    int tc = blockIdx.x, h = blockIdx.y, b = blockIdx.z;
    int tid = threadIdx.x;
    #pragma unroll
    for (int pass = 0; pass < 2; pass++) {
        const __nv_bfloat16* src = pass ? vl : vh;
        __nv_bfloat16* dst = pass ? vtl : vth;
        #pragma unroll
        for (int it = 0; it < 16; it++) {
            int idx = tid + it * 256;
            int r = idx >> 6, d = idx & 63;
            s[r][d] = src[(size_t)(b*Tt + tc*64 + r) * Ee + h*64 + d];
        }
        __syncthreads();
        #pragma unroll
        for (int it = 0; it < 16; it++) {
            int idx = tid + it * 256;
            int d = idx >> 6, c = idx & 63;
            dst[((size_t)(b*Hh + h)*64 + d) * Tt + tc*64 + c] = s[c][d];
        }
        __syncthreads();
    }
}

// ======================= HMMA split-bf16 GEMM ===============================
// C[N][M] = A[N][K] @ W[K][M]; A hi/lo bf16 [N][K], W hi/lo bf16 [M][K].
// 128x128x32 block tile, 256 thr (8 warps 2x4: 64x32), 2-stage cp.async.
#define T_AH 0
#define T_AL 10240
#define T_BH 20480
#define T_BL 30720
#define STAGE_B 40960
#define HG_SMEM (2 * STAGE_B)

template<int RELU, int BIAS, int RES, int OUTHL>
__global__ __launch_bounds__(256, 1) void hgemm_kernel(
    const __nv_bfloat16* __restrict__ Ah, const __nv_bfloat16* __restrict__ Al,
    const __nv_bfloat16* __restrict__ Bh, const __nv_bfloat16* __restrict__ Bl,
    const float* __restrict__ bias, const float* __restrict__ res,
    float* __restrict__ C, __nv_bfloat16* __restrict__ Chi,
    __nv_bfloat16* __restrict__ Clo, int K, int M)
{
    extern __shared__ char smem[];
    const uint32_t sb = smem_to_u32(smem);
    const int tid = threadIdx.x;
    const int wid = tid >> 5, lid = tid & 31;
    const int wr = wid >> 2, wc = wid & 3;
    const int row0 = blockIdx.y * 128, col0 = blockIdx.x * 128;

    const __nv_bfloat16* src[4] = {
        Ah + (size_t)row0 * K, Al + (size_t)row0 * K,
        Bh + (size_t)col0 * K, Bl + (size_t)col0 * K };

    const int ldr0 = tid >> 2, ldseg = (tid & 3);
    const uint32_t mrow = (uint32_t)(lid & 15);
    const uint32_t mcol = (uint32_t)(lid >> 4);
    const uint32_t aLane = (uint32_t)((wr * 64 + mrow) * 80 + mcol * 16);
    const uint32_t bLane = (uint32_t)((wc * 32 + mrow) * 80 + mcol * 16);

    float acc[4][4][4] = {};
    const int nchunk = K >> 5;

    auto issue = [&](int c, int stg) {
        const size_t k0 = (size_t)c * 32;
        #pragma unroll
        for (int t = 0; t < 4; t++) {
            const __nv_bfloat16* s = src[t] + k0;
            uint32_t dst = sb + stg * STAGE_B + t * 10240;
            #pragma unroll
            for (int i = 0; i < 2; i++) {
                int r = ldr0 + i * 64;
                cp_async16(dst + (uint32_t)(r * 80 + ldseg * 16),
                           s + (size_t)r * K + ldseg * 8);
            }
        }
        CP_COMMIT();
    };

    issue(0, 0);
    for (int c = 0; c < nchunk; c++) {
        if (c + 1 < nchunk) {
            issue(c + 1, (c + 1) & 1);
            CP_WAIT(1);
        } else {
            CP_WAIT(0);
        }
        __syncthreads();

        const uint32_t st = sb + (uint32_t)((c & 1) * STAGE_B);
        #pragma unroll
        for (int kk = 0; kk < 2; kk++) {
            const uint32_t ko = (uint32_t)(kk * 32);
            uint32_t ah[4][4], al[4][4], bh[2][4], bl[2][4];
            #pragma unroll
            for (int mi = 0; mi < 4; mi++) {
                ldmx4(ah[mi][0], ah[mi][1], ah[mi][2], ah[mi][3],
                      st + T_AH + aLane + (uint32_t)(mi * 1280) + ko);
                ldmx4(al[mi][0], al[mi][1], al[mi][2], al[mi][3],
                      st + T_AL + aLane + (uint32_t)(mi * 1280) + ko);
            }
            #pragma unroll
            for (int np = 0; np < 2; np++) {
                ldmx4(bh[np][0], bh[np][1], bh[np][2], bh[np][3],
                      st + T_BH + bLane + (uint32_t)(np * 1280) + ko);
                ldmx4(bl[np][0], bl[np][1], bl[np][2], bl[np][3],
                      st + T_BL + bLane + (uint32_t)(np * 1280) + ko);
            }
            #pragma unroll
            for (int mi = 0; mi < 4; mi++) {
                #pragma unroll
                for (int nj = 0; nj < 4; nj++) {
                    uint32_t h0 = bh[nj >> 1][nj & 1], h1 = bh[nj >> 1][(nj & 1) + 2];
                    uint32_t l0 = bl[nj >> 1][nj & 1], l1 = bl[nj >> 1][(nj & 1) + 2];
                    float* cc = acc[mi][nj];
                    mma16816(cc, ah[mi][0], ah[mi][1], ah[mi][2], ah[mi][3], h0, h1);
                    mma16816(cc, ah[mi][0], ah[mi][1], ah[mi][2], ah[mi][3], l0, l1);
                    mma16816(cc, al[mi][0], al[mi][1], al[mi][2], al[mi][3], h0, h1);
                }
            }
        }
        __syncthreads();
    }

    // epilogue
    const int l4 = lid >> 2, l2 = (lid & 3) * 2;
    #pragma unroll
    for (int mi = 0; mi < 4; mi++) {
        const int r = row0 + wr * 64 + mi * 16 + l4;
        #pragma unroll
        for (int nj = 0; nj < 4; nj++) {
            const int cgl = col0 + wc * 32 + nj * 8 + l2;
            float b0 = 0.f, b1 = 0.f;
            if (BIAS) { b0 = bias[cgl]; b1 = bias[cgl + 1]; }
            float v0 = acc[mi][nj][0] + b0, v1 = acc[mi][nj][1] + b1;
            float v2 = acc[mi][nj][2] + b0, v3 = acc[mi][nj][3] + b1;
            if (RELU) {
                v0 = fmaxf(v0, 0.f); v1 = fmaxf(v1, 0.f);
                v2 = fmaxf(v2, 0.f); v3 = fmaxf(v3, 0.f);
            }
            if (RES) {
                const float* r0p = res + (size_t)r * M + cgl;
                const float* r1p = res + (size_t)(r + 8) * M + cgl;
                v0 += r0p[0]; v1 += r0p[1];
                v2 += r1p[0]; v3 += r1p[1];
            }
            if (OUTHL) {
                *(uint32_t*)(Chi + (size_t)r * M + cgl)       = pk2(v0, v1);
                *(uint32_t*)(Clo + (size_t)r * M + cgl)       = pk2(blo(v0), blo(v1));
                *(uint32_t*)(Chi + (size_t)(r + 8) * M + cgl) = pk2(v2, v3);
                *(uint32_t*)(Clo + (size_t)(r + 8) * M + cgl) = pk2(blo(v2), blo(v3));
            } else {
                float2 o0 = {v0, v1}, o1 = {v2, v3};
                *(float2*)(C + (size_t)r * M + cgl) = o0;
                *(float2*)(C + (size_t)(r + 8) * M + cgl) = o1;
            }
        }
    }
}

// ======================= HMMA flash attention (split bf16) ==================
// BQ=64, BK=64, D=64, 128 threads (4 warps, each 16 q-rows).
// smem tiles row stride 72 bf16 (144B, conflict-free ldmatrix). Q/K/V hi+lo.
#define FQH 0
#define FQL 9216
#define FKH 18432
#define FKL 27648
#define FVH 36864
#define FVL 46080
#define FL_SMEM 55296

__global__ __launch_bounds__(128) void flash_mma_kernel(
    const __nv_bfloat16* __restrict__ qh, const __nv_bfloat16* __restrict__ ql,
    const __nv_bfloat16* __restrict__ kh, const __nv_bfloat16* __restrict__ kl,
    const __nv_bfloat16* __restrict__ vth, const __nv_bfloat16* __restrict__ vtl,
    __nv_bfloat16* __restrict__ atth, __nv_bfloat16* __restrict__ attl)
{
    extern __shared__ char smf[];
    const uint32_t sb = smem_to_u32(smf);
    const int qt = blockIdx.x, h = blockIdx.y, b = blockIdx.z;
    const int tid = threadIdx.x, wid = tid >> 5, lid = tid & 31;

    // cp.async tile load: 64 rows x 128B; thread -> row tid/2, 4 chunks
    const int lr = tid >> 1, lcb = (tid & 1) * 4;
    auto ldtile = [&](uint32_t off, const __nv_bfloat16* g, int gs) {
        #pragma unroll
        for (int i = 0; i < 4; i++)
            cp_async16(sb + off + (uint32_t)(lr * 144 + (lcb + i) * 16),
                       g + (size_t)lr * gs + (lcb + i) * 8);
    };

    const __nv_bfloat16* qsh = qh + ((size_t)(b*Tt + qt*64)) * Ee + h*64;
    const __nv_bfloat16* qsl = ql + ((size_t)(b*Tt + qt*64)) * Ee + h*64;
    const __nv_bfloat16* vbh = vth + ((size_t)(b*Hh + h) * 64) * Tt;
    const __nv_bfloat16* vbl = vtl + ((size_t)(b*Hh + h) * 64) * Tt;

    ldtile(FQH, qsh, Ee); ldtile(FQL, qsl, Ee);
    ldtile(FKH, kh + ((size_t)(b*Tt)) * Ee + h*64, Ee);
    ldtile(FKL, kl + ((size_t)(b*Tt)) * Ee + h*64, Ee);
    ldtile(FVH, vbh, Tt); ldtile(FVL, vbl, Tt);
    CP_COMMIT(); CP_WAIT(0);
    __syncthreads();

    // Q fragments held in registers for the whole kt loop
    const uint32_t arow = (uint32_t)(wid * 16 + (lid & 15));
    const uint32_t fcol = (uint32_t)((lid >> 4) * 16);
    uint32_t qfh[4][4], qfl[4][4];
    #pragma unroll
    for (int c = 0; c < 4; c++) {
        ldmx4(qfh[c][0], qfh[c][1], qfh[c][2], qfh[c][3],
              sb + FQH + arow * 144 + (uint32_t)(c * 32) + fcol);
        ldmx4(qfl[c][0], qfl[c][1], qfl[c][2], qfl[c][3],
              sb + FQL + arow * 144 + (uint32_t)(c * 32) + fcol);
    }

    const uint32_t brow = (uint32_t)(lid & 15);
    float oacc[8][4] = {};
    float m0 = -INFINITY, m1 = -INFINITY, l0 = 0.f, l1 = 0.f;

    const int rl0 = wid * 16 + (lid >> 2);    // local q row (elems 0,1)
    const int cl0 = (lid & 3) * 2;            // local col base within n8 tile

    for (int kt = 0; kt <= qt; kt++) {
        // ---- S = Q K^T (split bf16) ----
        float sacc[8][4] = {};
        #pragma unroll
        for (int c = 0; c < 4; c++) {
            uint32_t bh_[4][4], bl_[4][4];
            #pragma unroll
            for (int np = 0; np < 4; np++) {
                ldmx4(bh_[np][0], bh_[np][1], bh_[np][2], bh_[np][3],
                      sb + FKH + (uint32_t)((np*16 + brow) * 144 + c*32) + fcol);
                ldmx4(bl_[np][0], bl_[np][1], bl_[np][2], bl_[np][3],
                      sb + FKL + (uint32_t)((np*16 + brow) * 144 + c*32) + fcol);
            }
            #pragma unroll
            for (int np = 0; np < 4; np++) {
                #pragma unroll
                for (int hf = 0; hf < 2; hf++) {
                    uint32_t H0 = bh_[np][hf], H1 = bh_[np][hf + 2];
                    uint32_t L0 = bl_[np][hf], L1 = bl_[np][hf + 2];
                    float* cc = sacc[2*np + hf];
                    mma16816(cc, qfh[c][0], qfh[c][1], qfh[c][2], qfh[c][3], H0, H1);
                    mma16816(cc, qfh[c][0], qfh[c][1], qfh[c][2], qfh[c][3], L0, L1);
                    mma16816(cc, qfl[c][0], qfl[c][1], qfl[c][2], qfl[c][3], H0, H1);
                }
            }
        }

        // ---- causal mask on diagonal tile ----
        if (kt == qt) {
            #pragma unroll
            for (int j = 0; j < 8; j++) {
                int cb = j * 8 + cl0;
                #pragma unroll
                for (int e = 0; e < 4; e++) {
                    int cc = cb + (e & 1);
                    int rr = rl0 + ((e >= 2) ? 8 : 0);
                    if (cc > rr) sacc[j][e] = -INFINITY;
                }
            }
        }

        // ---- online softmax ----
        float mx0 = -INFINITY, mx1 = -INFINITY;
        #pragma unroll
        for (int j = 0; j < 8; j++) {
            mx0 = fmaxf(mx0, fmaxf(sacc[j][0], sacc[j][1]));
            mx1 = fmaxf(mx1, fmaxf(sacc[j][2], sacc[j][3]));
        }
        mx0 = fmaxf(mx0, __shfl_xor_sync(0xffffffffu, mx0, 1));
        mx0 = fmaxf(mx0, __shfl_xor_sync(0xffffffffu, mx0, 2));
        mx1 = fmaxf(mx1, __shfl_xor_sync(0xffffffffu, mx1, 1));
        mx1 = fmaxf(mx1, __shfl_xor_sync(0xffffffffu, mx1, 2));
        float mn0 = fmaxf(m0, mx0), mn1 = fmaxf(m1, mx1);
        float cr0 = __expf(m0 - mn0), cr1 = __expf(m1 - mn1);
        m0 = mn0; m1 = mn1;
        float s0 = 0.f, s1 = 0.f;
        #pragma unroll
        for (int j = 0; j < 8; j++) {
            sacc[j][0] = __expf(sacc[j][0] - mn0);
            sacc[j][1] = __expf(sacc[j][1] - mn0);
            sacc[j][2] = __expf(sacc[j][2] - mn1);
            sacc[j][3] = __expf(sacc[j][3] - mn1);
            s0 += sacc[j][0] + sacc[j][1];
            s1 += sacc[j][2] + sacc[j][3];
        }
        s0 += __shfl_xor_sync(0xffffffffu, s0, 1);
        s0 += __shfl_xor_sync(0xffffffffu, s0, 2);
        s1 += __shfl_xor_sync(0xffffffffu, s1, 1);
        s1 += __shfl_xor_sync(0xffffffffu, s1, 2);
        l0 = l0 * cr0 + s0;
        l1 = l1 * cr1 + s1;
        #pragma unroll
        for (int j = 0; j < 8; j++) {
            oacc[j][0] *= cr0; oacc[j][1] *= cr0;
            oacc[j][2] *= cr1; oacc[j][3] *= cr1;
        }

        // ---- P fragments (hi/lo) from sacc registers ----
        uint32_t pfh[4][4], pfl[4][4];
        #pragma unroll
        for (int kc = 0; kc < 4; kc++) {
            const float* pa = sacc[2*kc];
            const float* pb = sacc[2*kc + 1];
            pfh[kc][0] = pk2(pa[0], pa[1]);
            pfh[kc][1] = pk2(pa[2], pa[3]);
            pfh[kc][2] = pk2(pb[0], pb[1]);
            pfh[kc][3] = pk2(pb[2], pb[3]);
            pfl[kc][0] = pk2(blo(pa[0]), blo(pa[1]));
            pfl[kc][1] = pk2(blo(pa[2]), blo(pa[3]));
            pfl[kc][2] = pk2(blo(pb[0]), blo(pb[1]));
            pfl[kc][3] = pk2(blo(pb[2]), blo(pb[3]));
        }

        // ---- O += P V (split bf16) ----
        #pragma unroll
        for (int kc = 0; kc < 4; kc++) {
            uint32_t vh_[4][4], vl_[4][4];
            #pragma unroll
            for (int np = 0; np < 4; np++) {
                ldmx4(vh_[np][0], vh_[np][1], vh_[np][2], vh_[np][3],
                      sb + FVH + (uint32_t)((np*16 + brow) * 144 + kc*32) + fcol);
                ldmx4(vl_[np][0], vl_[np][1], vl_[np][2], vl_[np][3],
                      sb + FVL + (uint32_t)((np*16 + brow) * 144 + kc*32) + fcol);
            }
            #pragma unroll
            for (int np = 0; np < 4; np++) {
                #pragma unroll
                for (int hf = 0; hf < 2; hf++) {
                    uint32_t H0 = vh_[np][hf], H1 = vh_[np][hf + 2];
                    uint32_t L0 = vl_[np][hf], L1 = vl_[np][hf + 2];
                    float* cc = oacc[2*np + hf];
                    mma16816(cc, pfh[kc][0], pfh[kc][1], pfh[kc][2], pfh[kc][3], H0, H1);
                    mma16816(cc, pfh[kc][0], pfh[kc][1], pfh[kc][2], pfh[kc][3], L0, L1);
                    mma16816(cc, pfl[kc][0], pfl[kc][1], pfl[kc][2], pfl[kc][3], H0, H1);
                }
            }
        }

        // ---- next K/V tiles ----
        if (kt < qt) {
            __syncthreads();
            ldtile(FKH, kh + ((size_t)(b*Tt + (kt+1)*64)) * Ee + h*64, Ee);
            ldtile(FKL, kl + ((size_t)(b*Tt + (kt+1)*64)) * Ee + h*64, Ee);
            ldtile(FVH, vbh + (kt+1)*64, Tt);
            ldtile(FVL, vbl + (kt+1)*64, Tt);
            CP_COMMIT(); CP_WAIT(0);
            __syncthreads();
        }
    }

    // ---- epilogue: normalize, split hi/lo, store ----
    float i0 = 1.f / l0, i1 = 1.f / l1;
    const size_t r0 = (size_t)(b*Tt + qt*64 + rl0);
    #pragma unroll
    for (int j = 0; j < 8; j++) {
        int d0 = h*64 + j*8 + cl0;
        float o0 = oacc[j][0] * i0, o1 = oacc[j][1] * i0;
        float o2 = oacc[j][2] * i1, o3 = oacc[j][3] * i1;
        *(uint32_t*)(atth + r0 * Ee + d0)       = pk2(o0, o1);
        *(uint32_t*)(attl + r0 * Ee + d0)       = pk2(blo(o0), blo(o1));
        *(uint32_t*)(atth + (r0 + 8) * Ee + d0) = pk2(o2, o3);
        *(uint32_t*)(attl + (r0 + 8) * Ee + d0) = pk2(blo(o2), blo(o3));
    }
}

// ======================= orchestration ======================================
extern "C" void kernel_launch(void* const* d_in, const int* in_sizes, int n_in,
                              void* d_out, int out_size)
{
    (void)in_sizes; (void)n_in; (void)out_size;
    const float* x     = (const float*)d_in[0];
    const float* ln1_g = (const float*)d_in[1];
    const float* ln1_b = (const float*)d_in[2];
    const float* Wq    = (const float*)d_in[3];
    const float* Wk    = (const float*)d_in[4];
    const float* Wv    = (const float*)d_in[5];
    const float* Wo    = (const float*)d_in[6];
    const float* bo    = (const float*)d_in[7];
    const float* ln2_g = (const float*)d_in[8];
    const float* ln2_b = (const float*)d_in[9];
    const float* W1    = (const float*)d_in[10];
    const float* b1    = (const float*)d_in[11];
    const float* W2    = (const float*)d_in[12];
    const float* b2    = (const float*)d_in[13];
    float* out = (float*)d_out;

    float* x1;
    cudaGetSymbolAddress((void**)&x1, g_x1);

    __nv_bfloat16 *wqh,*wql,*wkh,*wkl,*wvh,*wvl,*woh,*wol,*w1h,*w1l,*w2h,*w2l;
    __nv_bfloat16 *ah,*al,*qh,*ql,*kh,*kl,*vh,*vl,*vth,*vtl,*atth,*attl,*hh,*hl;
    cudaGetSymbolAddress((void**)&wqh, g_wqh); cudaGetSymbolAddress((void**)&wql, g_wql);
    cudaGetSymbolAddress((void**)&wkh, g_wkh); cudaGetSymbolAddress((void**)&wkl, g_wkl);
    cudaGetSymbolAddress((void**)&wvh, g_wvh); cudaGetSymbolAddress((void**)&wvl, g_wvl);
    cudaGetSymbolAddress((void**)&woh, g_woh); cudaGetSymbolAddress((void**)&wol, g_wol);
    cudaGetSymbolAddress((void**)&w1h, g_w1h); cudaGetSymbolAddress((void**)&w1l, g_w1l);
    cudaGetSymbolAddress((void**)&w2h, g_w2h); cudaGetSymbolAddress((void**)&w2l, g_w2l);
    cudaGetSymbolAddress((void**)&ah,  g_ah);  cudaGetSymbolAddress((void**)&al,  g_al);
    cudaGetSymbolAddress((void**)&qh,  g_qh);  cudaGetSymbolAddress((void**)&ql,  g_ql);
    cudaGetSymbolAddress((void**)&kh,  g_kh);  cudaGetSymbolAddress((void**)&kl,  g_kl);
    cudaGetSymbolAddress((void**)&vh,  g_vh);  cudaGetSymbolAddress((void**)&vl,  g_vl);
    cudaGetSymbolAddress((void**)&vth, g_vth); cudaGetSymbolAddress((void**)&vtl, g_vtl);
    cudaGetSymbolAddress((void**)&atth,g_atth);cudaGetSymbolAddress((void**)&attl,g_attl);
    cudaGetSymbolAddress((void**)&hh,  g_hh);  cudaGetSymbolAddress((void**)&hl,  g_hl);

    cudaFuncSetAttribute(hgemm_kernel<0,0,0,1>, cudaFuncAttributeMaxDynamicSharedMemorySize, HG_SMEM);
    cudaFuncSetAttribute(hgemm_kernel<1,1,0,1>, cudaFuncAttributeMaxDynamicSharedMemorySize, HG_SMEM);
    cudaFuncSetAttribute(hgemm_kernel<0,1,1,0>, cudaFuncAttributeMaxDynamicSharedMemorySize, HG_SMEM);
    cudaFuncSetAttribute(flash_mma_kernel, cudaFuncAttributeMaxDynamicSharedMemorySize, FL_SMEM);

    dim3 tb(32, 8);
    dim3 gE(8, 32);
    dim3 gF(32, 32);

    // weight conversions (Wq pre-scaled by 1/sqrt(D))
    convT_hl_kernel<<<dim3(32, 32),  tb>>>(Wq, wqh, wql, Ee, Ee, 0.125f);
    convT_hl_kernel<<<dim3(32, 32),  tb>>>(Wk, wkh, wkl, Ee, Ee, 1.f);
    convT_hl_kernel<<<dim3(32, 32),  tb>>>(Wv, wvh, wvl, Ee, Ee, 1.f);
    convT_hl_kernel<<<dim3(32, 32),  tb>>>(Wo, woh, wol, Ee, Ee, 1.f);
    convT_hl_kernel<<<dim3(128, 32), tb>>>(W1, w1h, w1l, Ee, FF, 1.f);
    convT_hl_kernel<<<dim3(32, 128), tb>>>(W2, w2h, w2l, FF, Ee, 1.f);

    // 1) LN1 -> bf16 hi/lo
    ln_hl_kernel<<<Nn, 256>>>(x, ln1_g, ln1_b, ah, al);
    // 2-4) q/k/v (bf16 hi/lo outputs)
    hgemm_kernel<0,0,0,1><<<gE, 256, HG_SMEM>>>(ah, al, wqh, wql, nullptr, nullptr, nullptr, qh, ql, Ee, Ee);
    hgemm_kernel<0,0,0,1><<<gE, 256, HG_SMEM>>>(ah, al, wkh, wkl, nullptr, nullptr, nullptr, kh, kl, Ee, Ee);
    hgemm_kernel<0,0,0,1><<<gE, 256, HG_SMEM>>>(ah, al, wvh, wvl, nullptr, nullptr, nullptr, vh, vl, Ee, Ee);
    // 5) V transpose + flash attention
    vtrans_kernel<<<dim3(Tt/64, Hh, Bb), 256>>>(vh, vl, vth, vtl);
    flash_mma_kernel<<<dim3(Tt/64, Hh, Bb), 128, FL_SMEM>>>(qh, ql, kh, kl, vth, vtl, atth, attl);
    // 6) x1 = x + att @ Wo + bo
    hgemm_kernel<0,1,1,0><<<gE, 256, HG_SMEM>>>(atth, attl, woh, wol, bo, x, x1, nullptr, nullptr, Ee, Ee);
    // 7) LN2 -> bf16 hi/lo
    ln_hl_kernel<<<Nn, 256>>>(x1, ln2_g, ln2_b, hh, hl);
    // 8) ff = relu(h @ W1 + b1)  (bf16 hi/lo output)
    hgemm_kernel<1,1,0,1><<<gF, 256, HG_SMEM>>>(hh, hl, w1h, w1l, b1, nullptr, nullptr, ah, al, Ee, FF);
    // 9) out = x1 + ff @ W2 + b2
    hgemm_kernel<0,1,1,0><<<gE, 256, HG_SMEM>>>(ah, al, w2h, w2l, b2, x1, out, nullptr, nullptr, FF, Ee);
}